// round 4
// baseline (speedup 1.0000x reference)
#include <cuda_runtime.h>

#define BB       8
#define N_SMALL  12288
#define N_FULL   24576
#define CC       256
#define KK       4096
#define NT       1024
#define VPT      (N_FULL / NT)   // 24

// Global scratch (L2-resident, ~1.6 MB total)
__device__ int g_offs[BB * N_FULL];   // per-batch list END offsets
__device__ int g_list[BB * KK];       // packed (p<<15)|f grouped by target
__device__ int g_inv [BB * N_FULL];   // full-vertex -> image row, or -1

// ---------------------------------------------------------------------------
// Kernel 1 (8 CTAs): build per-target write lists + inv map. O(K+N) parallel.
// Reference scan, processing time p = 0..K-1 maps to order column k = K-1-p:
//    vf[T[p]] = vf[F[p]]
// ---------------------------------------------------------------------------
__global__ void __launch_bounds__(NT, 1)
build_kernel(const int* __restrict__ mask_idx,
             const int* __restrict__ order)
{
    extern __shared__ int smem[];
    int* offs    = smem;            // [N_FULL]
    int* scratch = smem + N_FULL;   // [32]

    const int b    = blockIdx.x;
    const int tid  = threadIdx.x;
    const int lane = tid & 31;
    const int wid  = tid >> 5;

    const int* of = order + b * 2 * KK;   // row 0 = f (column-indexed)
    const int* ot = of + KK;              // row 1 = t

    // inv init to -1 (global, per-CTA private region)
    int* inv = g_inv + b * N_FULL;
    for (int v = tid; v < N_FULL; v += NT) inv[v] = -1;

    // zero counts
    for (int v = tid; v < N_FULL; v += NT) offs[v] = 0;
    __syncthreads();

    // count writes per target (time p -> column KK-1-p)
    #pragma unroll
    for (int p = tid; p < KK; p += NT) atomicAdd(&offs[ot[KK - 1 - p]], 1);
    __syncthreads();

    // exclusive prefix scan of offs[N_FULL] in place
    {
        const int base = tid * VPT;
        int s = 0;
        #pragma unroll
        for (int i = 0; i < VPT; i++) s += offs[base + i];

        int incl = s;
        #pragma unroll
        for (int d = 1; d < 32; d <<= 1) {
            int n = __shfl_up_sync(0xFFFFFFFFu, incl, d);
            if (lane >= d) incl += n;
        }
        if (lane == 31) scratch[wid] = incl;
        __syncthreads();
        if (wid == 0) {
            int w  = scratch[lane];
            int wi = w;
            #pragma unroll
            for (int d = 1; d < 32; d <<= 1) {
                int n = __shfl_up_sync(0xFFFFFFFFu, wi, d);
                if (lane >= d) wi += n;
            }
            scratch[lane] = wi - w;
        }
        __syncthreads();
        int run = scratch[wid] + incl - s;
        #pragma unroll
        for (int i = 0; i < VPT; i++) {
            int c = offs[base + i];
            offs[base + i] = run;
            run += c;
        }
    }
    __syncthreads();

    // scatter packed (p<<15)|f; afterwards offs[v] = END of v's list
    int* listb = g_list + b * KK;
    #pragma unroll
    for (int p = tid; p < KK; p += NT) {
        int t   = ot[KK - 1 - p];
        int f   = of[KK - 1 - p];
        int pos = atomicAdd(&offs[t], 1);
        listb[pos] = (p << 15) | f;
    }
    __syncthreads();

    // publish ends, scatter mask into inv
    int* offb = g_offs + b * N_FULL;
    for (int v = tid; v < N_FULL; v += NT) offb[v] = offs[v];
    const int* mi = mask_idx + b * N_SMALL;
    for (int i = tid; i < N_SMALL; i += NT) inv[mi[i]] = i;
}

// ---------------------------------------------------------------------------
// Kernel 2: gather with on-the-fly provenance chase.
//   128 B (8 x float4) per thread -> 8 threads per 1 KB row.
//   Lane leader of each row-group chases; result broadcast via shfl.
//   Chase loads are L2-resident and latency-hidden by DRAM traffic.
// ---------------------------------------------------------------------------
__global__ void gather_kernel(const float4* __restrict__ img,
                              float4* __restrict__ out)
{
    const int t      = blockIdx.x * blockDim.x + threadIdx.x;
    const int rowIdx = t >> 3;              // 8 threads per row
    const int sub    = (t & 7) * 8;         // float4 offset within row
    const int b      = rowIdx / N_FULL;
    const int v      = rowIdx - b * N_FULL;
    const int lane   = threadIdx.x & 31;

    int row;
    if ((lane & 7) == 0) {
        const int* offb  = g_offs + b * N_FULL;
        const int* listb = g_list + b * KK;
        int cur = v, P = KK;
        for (;;) {
            int lo = cur ? __ldg(&offb[cur - 1]) : 0;
            int hi = __ldg(&offb[cur]);
            int best = -1;
            for (int e = lo; e < hi; e++) {
                int pv = __ldg(&listb[e]);
                if ((pv >> 15) < P && pv > best) best = pv;
            }
            if (best < 0) break;
            cur = best & 0x7FFF;
            P   = best >> 15;
        }
        row = __ldg(&g_inv[b * N_FULL + cur]);
    }
    row = __shfl_sync(0xFFFFFFFFu, row, lane & ~7);

    const size_t obase = (size_t)rowIdx * 64 + sub;
    if (row >= 0) {
        const float4* src = img + ((size_t)b * N_SMALL + row) * 64 + sub;
        float4 v0 = __ldg(src + 0);
        float4 v1 = __ldg(src + 1);
        float4 v2 = __ldg(src + 2);
        float4 v3 = __ldg(src + 3);
        float4 v4 = __ldg(src + 4);
        float4 v5 = __ldg(src + 5);
        float4 v6 = __ldg(src + 6);
        float4 v7 = __ldg(src + 7);
        __stcs(out + obase + 0, v0);
        __stcs(out + obase + 1, v1);
        __stcs(out + obase + 2, v2);
        __stcs(out + obase + 3, v3);
        __stcs(out + obase + 4, v4);
        __stcs(out + obase + 5, v5);
        __stcs(out + obase + 6, v6);
        __stcs(out + obase + 7, v7);
    } else {
        const float4 z = make_float4(0.f, 0.f, 0.f, 0.f);
        #pragma unroll
        for (int i = 0; i < 8; i++) __stcs(out + obase + i, z);
    }
}

extern "C" void kernel_launch(void* const* d_in, const int* in_sizes, int n_in,
                              void* d_out, int out_size)
{
    const float* images   = (const float*)d_in[0];
    const int*   mask_idx = (const int*)d_in[1];
    const int*   order    = (const int*)d_in[2];
    float* out = (float*)d_out;

    const int smem_bytes = (N_FULL + 32) * (int)sizeof(int);   // ~96 KB
    cudaFuncSetAttribute(build_kernel,
                         cudaFuncAttributeMaxDynamicSharedMemorySize,
                         smem_bytes);

    build_kernel<<<BB, NT, smem_bytes>>>(mask_idx, order);

    const int nthreads = BB * N_FULL * 8;   // 8 threads per row
    gather_kernel<<<nthreads / 256, 256>>>((const float4*)images, (float4*)out);
}

// round 5
// speedup vs baseline: 1.2772x; 1.2772x over previous
#include <cuda_runtime.h>

#define BB       8
#define N_SMALL  12288
#define N_FULL   24576
#define CC       256
#define KK       4096
#define NT       1024
#define VPT      (N_FULL / NT)   // 24

// Global scratch (~1.6 MB, L2-resident)
__device__ int g_offs[BB * N_FULL];   // per-batch list END offsets
__device__ int g_list[BB * KK];       // packed (p<<15)|f grouped by target
__device__ int g_inv [BB * N_FULL];   // full-vertex -> image row, or -1
__device__ int g_row [BB * N_FULL];   // final: output row -> image row, or -1

// ---------------------------------------------------------------------------
// Kernel 1 (8 CTAs): counting-sort build of per-target write lists + inv map.
// Reference scan at processing time p = 0..K-1 (order column k = K-1-p):
//    vf[T[p]] = vf[F[p]]
// ---------------------------------------------------------------------------
__global__ void __launch_bounds__(NT, 1)
build_kernel(const int* __restrict__ mask_idx,
             const int* __restrict__ order)
{
    extern __shared__ int smem[];
    int* offs    = smem;            // [N_FULL]
    int* scratch = smem + N_FULL;   // [32]

    const int b    = blockIdx.x;
    const int tid  = threadIdx.x;
    const int lane = tid & 31;
    const int wid  = tid >> 5;

    const int* of = order + b * 2 * KK;   // row 0 = f
    const int* ot = of + KK;              // row 1 = t

    int* inv = g_inv + b * N_FULL;
    for (int v = tid; v < N_FULL; v += NT) inv[v] = -1;

    for (int v = tid; v < N_FULL; v += NT) offs[v] = 0;
    __syncthreads();

    // count writes per target
    for (int p = tid; p < KK; p += NT) atomicAdd(&offs[ot[KK - 1 - p]], 1);
    __syncthreads();

    // exclusive prefix scan of offs[N_FULL] in place
    {
        const int base = tid * VPT;
        int s = 0;
        #pragma unroll
        for (int i = 0; i < VPT; i++) s += offs[base + i];

        int incl = s;
        #pragma unroll
        for (int d = 1; d < 32; d <<= 1) {
            int n = __shfl_up_sync(0xFFFFFFFFu, incl, d);
            if (lane >= d) incl += n;
        }
        if (lane == 31) scratch[wid] = incl;
        __syncthreads();
        if (wid == 0) {
            int w  = scratch[lane];
            int wi = w;
            #pragma unroll
            for (int d = 1; d < 32; d <<= 1) {
                int n = __shfl_up_sync(0xFFFFFFFFu, wi, d);
                if (lane >= d) wi += n;
            }
            scratch[lane] = wi - w;
        }
        __syncthreads();
        int run = scratch[wid] + incl - s;
        #pragma unroll
        for (int i = 0; i < VPT; i++) {
            int c = offs[base + i];
            offs[base + i] = run;
            run += c;
        }
    }
    __syncthreads();

    // scatter packed (p<<15)|f; afterwards offs[v] = END of v's list
    int* listb = g_list + b * KK;
    for (int p = tid; p < KK; p += NT) {
        int t   = ot[KK - 1 - p];
        int f   = of[KK - 1 - p];
        int pos = atomicAdd(&offs[t], 1);
        listb[pos] = (p << 15) | f;
    }
    __syncthreads();

    int* offb = g_offs + b * N_FULL;
    for (int v = tid; v < N_FULL; v += NT) offb[v] = offs[v];
    const int* mi = mask_idx + b * N_SMALL;
    for (int i = tid; i < N_SMALL; i += NT) inv[mi[i]] = i;
}

// ---------------------------------------------------------------------------
// Kernel 2 (wide): one thread per (b, v) — parallel provenance chase.
//   Avg list length K/N = 0.17, expected hops ~1.2; L2-resident scratch.
// ---------------------------------------------------------------------------
__global__ void chase_kernel()
{
    const int t = blockIdx.x * blockDim.x + threadIdx.x;
    if (t >= BB * N_FULL) return;
    const int b = t / N_FULL;
    const int v = t - b * N_FULL;

    const int* offb  = g_offs + b * N_FULL;
    const int* listb = g_list + b * KK;

    int cur = v, P = KK;
    for (;;) {
        int lo = cur ? __ldg(&offb[cur - 1]) : 0;
        int hi = __ldg(&offb[cur]);
        int best = -1;
        for (int e = lo; e < hi; e++) {
            int pv = __ldg(&listb[e]);
            if ((pv >> 15) < P && pv > best) best = pv;
        }
        if (best < 0) break;
        cur = best & 0x7FFF;
        P   = best >> 15;
    }
    g_row[t] = __ldg(&g_inv[b * N_FULL + cur]);
}

// ---------------------------------------------------------------------------
// Kernel 3: vectorized row gather, 4 x float4 (64B) per thread (R3 form).
// ---------------------------------------------------------------------------
__global__ void gather_kernel(const float4* __restrict__ img,
                              float4* __restrict__ out)
{
    const int t      = blockIdx.x * blockDim.x + threadIdx.x;
    const int idx4   = t * 4;              // first float4 index
    const int rowIdx = idx4 >> 6;          // 64 float4 per row (C=256)
    const int q      = idx4 & 63;
    const int b      = rowIdx / N_FULL;
    const int row    = __ldg(&g_row[rowIdx]);

    float4 v0, v1, v2, v3;
    if (row >= 0) {
        const float4* src = img + ((size_t)b * N_SMALL + row) * 64 + q;
        v0 = __ldg(src + 0);
        v1 = __ldg(src + 1);
        v2 = __ldg(src + 2);
        v3 = __ldg(src + 3);
    } else {
        v0 = v1 = v2 = v3 = make_float4(0.f, 0.f, 0.f, 0.f);
    }
    __stcs(out + idx4 + 0, v0);
    __stcs(out + idx4 + 1, v1);
    __stcs(out + idx4 + 2, v2);
    __stcs(out + idx4 + 3, v3);
}

extern "C" void kernel_launch(void* const* d_in, const int* in_sizes, int n_in,
                              void* d_out, int out_size)
{
    const float* images   = (const float*)d_in[0];
    const int*   mask_idx = (const int*)d_in[1];
    const int*   order    = (const int*)d_in[2];
    float* out = (float*)d_out;

    const int smem_bytes = (N_FULL + 32) * (int)sizeof(int);   // ~96 KB
    cudaFuncSetAttribute(build_kernel,
                         cudaFuncAttributeMaxDynamicSharedMemorySize,
                         smem_bytes);

    build_kernel<<<BB, NT, smem_bytes>>>(mask_idx, order);

    chase_kernel<<<(BB * N_FULL + 255) / 256, 256>>>();

    const int total4 = BB * N_FULL * (CC / 4);   // 12,582,912 float4
    gather_kernel<<<total4 / 4 / 256, 256>>>((const float4*)images, (float4*)out);
}

// round 6
// speedup vs baseline: 1.4725x; 1.1529x over previous
#include <cuda_runtime.h>

#define BB       8
#define N_SMALL  12288
#define N_FULL   24576
#define CC       256
#define KK       4096
#define SLOTS    16            // max writes tracked per vertex (Poisson(1/6) -> safe)

// Global scratch (~14 MB, L2-resident working set much smaller)
__device__ int g_cnt  [BB * N_FULL];          // writes per vertex
__device__ int g_slots[BB * N_FULL * SLOTS];  // packed (p<<15)|f, unordered
__device__ int g_inv  [BB * N_FULL];          // full-vertex -> image row, or -1
__device__ int g_row  [BB * N_FULL];          // output row -> image row, or -1

// ---------------------------------------------------------------------------
// K1: full-grid init. cnt = 0, inv = -1.
// ---------------------------------------------------------------------------
__global__ void init_kernel()
{
    const int t = blockIdx.x * blockDim.x + threadIdx.x;
    if (t < BB * N_FULL) {
        g_cnt[t] = 0;
        g_inv[t] = -1;
    }
}

// ---------------------------------------------------------------------------
// K2: full-grid fill.
//   Threads [0, B*K):        bucket the write events.
//     Reference scan at time p = 0..K-1 executes vf[T[p]] = vf[F[p]],
//     where F[p] = order[b,0,K-1-p], T[p] = order[b,1,K-1-p].
//   Threads [B*K, B*K+B*N_SMALL): scatter mask_idx into inv.
// ---------------------------------------------------------------------------
__global__ void fill_kernel(const int* __restrict__ mask_idx,
                            const int* __restrict__ order)
{
    const int t = blockIdx.x * blockDim.x + threadIdx.x;
    if (t < BB * KK) {
        const int b = t / KK;
        const int p = t - b * KK;          // processing time
        const int k = KK - 1 - p;          // order column
        const int f = order[b * 2 * KK + k];
        const int v = order[b * 2 * KK + KK + k];
        const int idx  = b * N_FULL + v;
        const int slot = atomicAdd(&g_cnt[idx], 1);
        if (slot < SLOTS)                   // overflow prob ~1e-20
            g_slots[(idx << 4) + slot] = (p << 15) | f;
    } else {
        const int u = t - BB * KK;
        if (u < BB * N_SMALL) {
            const int b = u / N_SMALL;
            const int i = u - b * N_SMALL;
            g_inv[b * N_FULL + mask_idx[u]] = i;
        }
    }
}

// ---------------------------------------------------------------------------
// K3: one thread per (b, v) — parallel provenance chase.
//   chase(v, P): among writes to v with time < P pick the latest; hop to its
//   source with the new bound; stop when none. Expected hops ~1.2.
// ---------------------------------------------------------------------------
__global__ void chase_kernel()
{
    const int t = blockIdx.x * blockDim.x + threadIdx.x;
    if (t >= BB * N_FULL) return;
    const int b    = t / N_FULL;
    const int base = b * N_FULL;

    int cur = t - base, P = KK;
    for (;;) {
        const int idx = base + cur;
        const int n   = __ldg(&g_cnt[idx]);
        int best = -1;
        for (int j = 0; j < n; j++) {
            int pv = __ldg(&g_slots[(idx << 4) + j]);
            if ((pv >> 15) < P && pv > best) best = pv;
        }
        if (best < 0) break;
        cur = best & 0x7FFF;
        P   = best >> 15;
    }
    g_row[t] = __ldg(&g_inv[base + cur]);
}

// ---------------------------------------------------------------------------
// K4: vectorized row gather, 4 x float4 (64B) per thread.
//   out[b, v, :] = row >= 0 ? images[b, row, :] : 0
// ---------------------------------------------------------------------------
__global__ void gather_kernel(const float4* __restrict__ img,
                              float4* __restrict__ out)
{
    const int t      = blockIdx.x * blockDim.x + threadIdx.x;
    const int idx4   = t * 4;              // first float4 index
    const int rowIdx = idx4 >> 6;          // 64 float4 per row (C=256)
    const int q      = idx4 & 63;
    const int b      = rowIdx / N_FULL;
    const int row    = __ldg(&g_row[rowIdx]);

    float4 v0, v1, v2, v3;
    if (row >= 0) {
        const float4* src = img + ((size_t)b * N_SMALL + row) * 64 + q;
        v0 = __ldg(src + 0);
        v1 = __ldg(src + 1);
        v2 = __ldg(src + 2);
        v3 = __ldg(src + 3);
    } else {
        v0 = v1 = v2 = v3 = make_float4(0.f, 0.f, 0.f, 0.f);
    }
    __stcs(out + idx4 + 0, v0);
    __stcs(out + idx4 + 1, v1);
    __stcs(out + idx4 + 2, v2);
    __stcs(out + idx4 + 3, v3);
}

extern "C" void kernel_launch(void* const* d_in, const int* in_sizes, int n_in,
                              void* d_out, int out_size)
{
    const float* images   = (const float*)d_in[0];
    const int*   mask_idx = (const int*)d_in[1];
    const int*   order    = (const int*)d_in[2];
    float* out = (float*)d_out;

    init_kernel<<<(BB * N_FULL + 255) / 256, 256>>>();

    const int fill_threads = BB * KK + BB * N_SMALL;   // 131072
    fill_kernel<<<(fill_threads + 255) / 256, 256>>>(mask_idx, order);

    chase_kernel<<<(BB * N_FULL + 255) / 256, 256>>>();

    const int total4 = BB * N_FULL * (CC / 4);   // 12,582,912 float4
    gather_kernel<<<total4 / 4 / 256, 256>>>((const float4*)images, (float4*)out);
}

// round 7
// speedup vs baseline: 1.6043x; 1.0895x over previous
#include <cuda_runtime.h>

#define BB       8
#define N_SMALL  12288
#define N_FULL   24576
#define CC       256
#define KK       4096
#define SLOTS    8             // max writes tracked per vertex (Poisson(1/6))

// Global scratch (~7.6 MB)
__device__ int g_cnt  [BB * N_FULL];          // writes per vertex
__device__ int g_slots[BB * N_FULL * SLOTS];  // packed (p<<15)|f, unordered
__device__ int g_inv  [BB * N_FULL];          // full-vertex -> image row, or -1
__device__ int g_row  [BB * N_FULL];          // output row -> image row, or -1

// ---------------------------------------------------------------------------
// K1: full-grid init. cnt = 0, inv = -1.
// ---------------------------------------------------------------------------
__global__ void init_kernel()
{
    const int t = blockIdx.x * blockDim.x + threadIdx.x;
    if (t < BB * N_FULL) {
        g_cnt[t] = 0;
        g_inv[t] = -1;
    }
}

// ---------------------------------------------------------------------------
// K2: full-grid fill.
//   Threads [0, B*K): bucket write events. Reference scan at time p = 0..K-1
//   executes vf[T[p]] = vf[F[p]], F[p] = order[b,0,K-1-p], T[p] = order[b,1,K-1-p].
//   Threads [B*K, ...): scatter mask_idx into inv.
// ---------------------------------------------------------------------------
__global__ void fill_kernel(const int* __restrict__ mask_idx,
                            const int* __restrict__ order)
{
    const int t = blockIdx.x * blockDim.x + threadIdx.x;
    if (t < BB * KK) {
        const int b = t / KK;
        const int p = t - b * KK;          // processing time
        const int k = KK - 1 - p;          // order column
        const int f = order[b * 2 * KK + k];
        const int v = order[b * 2 * KK + KK + k];
        const int idx  = b * N_FULL + v;
        const int slot = atomicAdd(&g_cnt[idx], 1);
        if (slot < SLOTS)                   // overflow prob ~5e-8 per run
            __stcs(&g_slots[idx * SLOTS + slot], (p << 15) | f);
    } else {
        const int u = t - BB * KK;
        if (u < BB * N_SMALL) {
            const int b = u / N_SMALL;
            const int i = u - b * N_SMALL;
            g_inv[b * N_FULL + mask_idx[u]] = i;
        }
    }
}

// ---------------------------------------------------------------------------
// K3: one thread per (b, v) — parallel provenance chase.
//   chase(v, P): among writes to v with time < P pick the latest; hop to its
//   source with the new bound; stop when none. Expected hops ~1.2.
// ---------------------------------------------------------------------------
__global__ void chase_kernel()
{
    const int t = blockIdx.x * blockDim.x + threadIdx.x;
    if (t >= BB * N_FULL) return;
    const int b    = t / N_FULL;
    const int base = b * N_FULL;

    int cur = t - base, P = KK;
    for (;;) {
        const int idx = base + cur;
        const int n   = __ldg(&g_cnt[idx]);
        int best = -1;
        for (int j = 0; j < n; j++) {
            int pv = __ldg(&g_slots[idx * SLOTS + j]);
            if ((pv >> 15) < P && pv > best) best = pv;
        }
        if (best < 0) break;
        cur = best & 0x7FFF;
        P   = best >> 15;
    }
    g_row[t] = __ldg(&g_inv[base + cur]);
}

// ---------------------------------------------------------------------------
// K4: row gather with TWO independent chains per thread.
//   Thread t serves 2 float4 (32B) in the FIRST half of the output and
//   2 float4 in the SECOND half (rows 98304 apart). Two independent
//   index->data dependency chains double memory-level parallelism.
//   A warp covers one contiguous 1 KB row per segment (index is
//   warp-uniform, accesses fully coalesced).
// ---------------------------------------------------------------------------
#define HALF4 (BB * N_FULL * (CC / 4) / 2)   // 6,291,456 float4 per half

__global__ void gather_kernel(const float4* __restrict__ img,
                              float4* __restrict__ out)
{
    const int t    = blockIdx.x * blockDim.x + threadIdx.x;
    const int i4   = t * 2;               // first float4 index (half-local)
    const int rA   = i4 >> 6;             // row in first half
    const int q    = i4 & 63;             // float4 offset within row
    const int rB   = rA + (BB * N_FULL / 2);

    // independent index loads (both warp-uniform broadcasts)
    const int rowA = __ldg(&g_row[rA]);
    const int rowB = __ldg(&g_row[rB]);

    const int bA = rA / N_FULL;
    const int bB = rB / N_FULL;

    float4 a0, a1, b0, b1;
    const float4 z = make_float4(0.f, 0.f, 0.f, 0.f);

    if (rowA >= 0) {
        const float4* s = img + ((size_t)bA * N_SMALL + rowA) * 64 + q;
        a0 = __ldg(s + 0);
        a1 = __ldg(s + 1);
    } else { a0 = a1 = z; }

    if (rowB >= 0) {
        const float4* s = img + ((size_t)bB * N_SMALL + rowB) * 64 + q;
        b0 = __ldg(s + 0);
        b1 = __ldg(s + 1);
    } else { b0 = b1 = z; }

    __stcs(out + i4 + 0, a0);
    __stcs(out + i4 + 1, a1);
    __stcs(out + HALF4 + i4 + 0, b0);
    __stcs(out + HALF4 + i4 + 1, b1);
}

extern "C" void kernel_launch(void* const* d_in, const int* in_sizes, int n_in,
                              void* d_out, int out_size)
{
    const float* images   = (const float*)d_in[0];
    const int*   mask_idx = (const int*)d_in[1];
    const int*   order    = (const int*)d_in[2];
    float* out = (float*)d_out;

    init_kernel<<<(BB * N_FULL + 255) / 256, 256>>>();

    const int fill_threads = BB * KK + BB * N_SMALL;   // 131072
    fill_kernel<<<(fill_threads + 255) / 256, 256>>>(mask_idx, order);

    chase_kernel<<<(BB * N_FULL + 255) / 256, 256>>>();

    const int nthreads = HALF4 / 2;        // 3,145,728 threads
    gather_kernel<<<nthreads / 256, 256>>>((const float4*)images, (float4*)out);
}